// round 5
// baseline (speedup 1.0000x reference)
#include <cuda_runtime.h>
#include <cuda_bf16.h>
#include <cstdint>

#define NN   50000
#define NE   800000
#define NG   64
#define CH   64
#define INCH 128
#define SCAN_B 1024
#define NB   ((NN + SCAN_B - 1) / SCAN_B)   // 49

// ---------------- scratch (static device globals; no allocation) -------------
struct PreZero { float wdeg[NN]; int deg[NN]; };        // zeroed by one memset
struct PoolZero { unsigned maxk[NG * CH]; float sum[NG * CH]; float cnt[NG]; };
__device__ PreZero  g_pz;
__device__ PoolZero g_po;
__device__ float g_dinv[NN];
__device__ float g_selfc[NN];
__device__ int   g_rowptr[NN];
__device__ int   g_fill[NN];
__device__ int   g_bsum[64];
__device__ int2  g_edge[NE];                 // CSR-sorted (src, norm-bits)
__device__ __align__(16) float g_h[NN * CH];   // h = act @ W
__device__ __align__(16) float g_act[NN * CH]; // tanh(layer output)

// ---------------- helpers ----------------------------------------------------
__device__ __forceinline__ float acc_tanh(float x) {
    float e = __expf(-2.0f * fabsf(x));
    float t = __fdividef(1.0f - e, 1.0f + e);
    return copysignf(t, x);
}
// monotonic unsigned key: init 0 == "below any real float"
__device__ __forceinline__ unsigned ukey(float f) {
    unsigned u = __float_as_uint(f);
    return (u & 0x80000000u) ? ~u : (u | 0x80000000u);
}
__device__ __forceinline__ float udec(unsigned u) {
    return __uint_as_float((u & 0x80000000u) ? (u & 0x7FFFFFFFu) : ~u);
}

#define FMA2(d, a, b) asm("fma.rn.f32x2 %0, %1, %2, %0;" : "+l"(d) : "l"(a), "l"(b))
__device__ __forceinline__ unsigned long long pack2(float x) {
    unsigned long long r;
    unsigned xi = __float_as_uint(x);
    asm("mov.b64 %0, {%1, %1};" : "=l"(r) : "r"(xi));
    return r;
}
__device__ __forceinline__ float2 unpack2(unsigned long long v) {
    unsigned lo, hi;
    asm("mov.b64 {%0, %1}, %2;" : "=r"(lo), "=r"(hi) : "l"(v));
    return make_float2(__uint_as_float(lo), __uint_as_float(hi));
}

// ---------------- preprocessing ----------------------------------------------
__global__ void k_pre_deg(const int* __restrict__ ei, const float* __restrict__ w) {
    int e = blockIdx.x * blockDim.x + threadIdx.x;
    if (e < NE) {
        int dst = ei[NE + e];
        atomicAdd(&g_pz.wdeg[dst], w[e]);
        atomicAdd(&g_pz.deg[dst], 1);
    }
}

// warp-shuffle scan over 1024 elems; also computes dinv/selfc (independent work)
__global__ void k_scan_block() {
    __shared__ int wsum[32];
    int tid = threadIdx.x;
    int i   = blockIdx.x * SCAN_B + tid;
    int lane = tid & 31, wid = tid >> 5;
    int v = (i < NN) ? g_pz.deg[i] : 0;
    int s = v;
#pragma unroll
    for (int o = 1; o < 32; o <<= 1) {
        int t = __shfl_up_sync(0xFFFFFFFFu, s, o);
        if (lane >= o) s += t;
    }
    if (lane == 31) wsum[wid] = s;
    __syncthreads();
    if (wid == 0) {
        int ws = wsum[lane];
#pragma unroll
        for (int o = 1; o < 32; o <<= 1) {
            int t = __shfl_up_sync(0xFFFFFFFFu, ws, o);
            if (lane >= o) ws += t;
        }
        wsum[lane] = ws;
    }
    __syncthreads();
    int off = wid ? wsum[wid - 1] : 0;
    if (i < NN) g_rowptr[i] = off + s - v;           // exclusive, pre-offset
    if (tid == SCAN_B - 1) g_bsum[blockIdx.x] = off + s;

    if (i < NN) {
        float r = rsqrtf(g_pz.wdeg[i] + 1.0f);       // +1 self-loop weight
        g_dinv[i]  = r;
        g_selfc[i] = r * r;
    }
}

__global__ void k_scan_carry() {
    __shared__ int s[64];
    int tid = threadIdx.x;   // 64 threads
    int v = (tid < NB) ? g_bsum[tid] : 0;
    s[tid] = v; __syncthreads();
#pragma unroll
    for (int o = 1; o < 64; o <<= 1) {
        int t = (tid >= o) ? s[tid - o] : 0;
        __syncthreads();
        s[tid] += t;
        __syncthreads();
    }
    if (tid < NB) g_bsum[tid] = s[tid] - v;      // exclusive block offsets
}

__global__ void k_scan_add() {
    int i = blockIdx.x * blockDim.x + threadIdx.x;
    if (i < NN) {
        int rp = g_rowptr[i] + g_bsum[i >> 10];
        g_rowptr[i] = rp;
        g_fill[i]   = rp;
    }
}

__global__ void k_place(const int* __restrict__ ei, const float* __restrict__ w) {
    int e = blockIdx.x * blockDim.x + threadIdx.x;
    if (e < NE) {
        int src = ei[e];
        int dst = ei[NE + e];
        float nm = g_dinv[src] * w[e] * g_dinv[dst];
        int pos = atomicAdd(&g_fill[dst], 1);
        g_edge[pos] = make_int2(src, __float_as_int(nm));
    }
}

// ---------------- GEMM: h = A @ W (packed f32x2 FMA, transposed A tile) --------
// 256 threads; block = 64 rows x 64 cols; thread = 4 rows x 4 cols.
template <int K, bool FROM_ACT>
__global__ void k_gemm(const float* __restrict__ in, const float* __restrict__ W) {
    __shared__ float sA[64 * 68];    // transposed: sA[k*68 + row]
    __shared__ float sW[64 * 64];    // sW[k*64 + col]

    const int tid  = threadIdx.x;
    const int row0 = blockIdx.x * 64;
    const int rowg = tid >> 4;    // 0..15, 4 rows each
    const int colg = tid & 15;    // 0..15, 4 cols each

    const float* A = FROM_ACT ? (const float*)g_act : in;

    unsigned long long acc[4][2] = {{0ull,0ull},{0ull,0ull},{0ull,0ull},{0ull,0ull}};

    for (int kc = 0; kc < K; kc += 64) {
        // stage A tile transposed: read (row, k4) float4, write 4 scalars
#pragma unroll
        for (int idx = tid; idx < 64 * 16; idx += 256) {
            int rr = idx >> 4, k4 = (idx & 15) * 4;
            int grow = row0 + rr;
            float4 v = make_float4(0.f, 0.f, 0.f, 0.f);
            if (grow < NN) v = *(const float4*)(A + (size_t)grow * K + kc + k4);
            sA[(k4 + 0) * 68 + rr] = v.x;
            sA[(k4 + 1) * 68 + rr] = v.y;
            sA[(k4 + 2) * 68 + rr] = v.z;
            sA[(k4 + 3) * 68 + rr] = v.w;
        }
        // stage W chunk (already k-major)
#pragma unroll
        for (int idx = tid; idx < 64 * 16; idx += 256) {
            int rr = idx >> 4, c4 = (idx & 15) * 4;
            *(float4*)(sW + rr * 64 + c4) = *(const float4*)(W + (size_t)(kc + rr) * 64 + c4);
        }
        __syncthreads();

#pragma unroll
        for (int k = 0; k < 64; ++k) {
            const float4 av = *(const float4*)(sA + k * 68 + rowg * 4);
            const ulonglong2 wv = *(const ulonglong2*)(sW + k * 64 + colg * 4);
            unsigned long long pa0 = pack2(av.x), pa1 = pack2(av.y);
            unsigned long long pa2 = pack2(av.z), pa3 = pack2(av.w);
            FMA2(acc[0][0], pa0, wv.x); FMA2(acc[0][1], pa0, wv.y);
            FMA2(acc[1][0], pa1, wv.x); FMA2(acc[1][1], pa1, wv.y);
            FMA2(acc[2][0], pa2, wv.x); FMA2(acc[2][1], pa2, wv.y);
            FMA2(acc[3][0], pa3, wv.x); FMA2(acc[3][1], pa3, wv.y);
        }
        __syncthreads();
    }

    int row = row0 + rowg * 4;
#pragma unroll
    for (int i = 0; i < 4; ++i) {
        if (row + i < NN) {
            float2 lo = unpack2(acc[i][0]);
            float2 hi = unpack2(acc[i][1]);
            *(float4*)(g_h + (size_t)(row + i) * CH + colg * 4) =
                make_float4(lo.x, lo.y, hi.x, hi.y);
        }
    }
}

// ------- gather: act[i] = tanh(b + selfc[i]*h[i] + sum_e norm*h[src]) ----------
// one warp per node; 2 edges per iteration; lane = (half, c4): float4 channels.
__global__ void k_gather(const float* __restrict__ b) {
    int warp = (blockIdx.x * blockDim.x + threadIdx.x) >> 5;
    int lane = threadIdx.x & 31;
    if (warp >= NN) return;
    const int node = warp;
    const int beg  = g_rowptr[node];
    const int deg  = g_pz.deg[node];
    const int half = lane >> 4;
    const int c4   = (lane & 15) * 4;

    float ax = 0.f, ay = 0.f, az = 0.f, aw = 0.f;
    for (int ch = 0; ch < deg; ch += 32) {
        int rem = deg - ch;
        int n = rem < 32 ? rem : 32;
        int s = node; float nm = 0.0f;     // inactive lanes: nm=0 contributes nothing
        if (lane < n) {
            int2 e = g_edge[beg + ch + lane];
            s = e.x; nm = __int_as_float(e.y);
        }
        int npairs = (n + 1) >> 1;
#pragma unroll 4
        for (int j = 0; j < npairs; ++j) {
            int   se = __shfl_sync(0xFFFFFFFFu, s,  2 * j + half);
            float ne = __shfl_sync(0xFFFFFFFFu, nm, 2 * j + half);
            float4 hv = *(const float4*)(g_h + (size_t)se * CH + c4);
            ax += ne * hv.x; ay += ne * hv.y; az += ne * hv.z; aw += ne * hv.w;
        }
    }
    // combine the two edge-parity halves
    ax += __shfl_xor_sync(0xFFFFFFFFu, ax, 16);
    ay += __shfl_xor_sync(0xFFFFFFFFu, ay, 16);
    az += __shfl_xor_sync(0xFFFFFFFFu, az, 16);
    aw += __shfl_xor_sync(0xFFFFFFFFu, aw, 16);

    if (half == 0) {
        float sc = g_selfc[node];
        float4 hs = *(const float4*)(g_h + (size_t)node * CH + c4);
        float4 bb = *(const float4*)(b + c4);
        float4 o;
        o.x = acc_tanh(bb.x + sc * hs.x + ax);
        o.y = acc_tanh(bb.y + sc * hs.y + ay);
        o.z = acc_tanh(bb.z + sc * hs.z + az);
        o.w = acc_tanh(bb.w + sc * hs.w + aw);
        *(float4*)(g_act + (size_t)node * CH + c4) = o;
    }
}

// ---------------- pooling (g_act already tanh'd; g_po memset to 0) -------------
__device__ __forceinline__ void pool_flush(int g, int c, float mx, float sm, int cnt) {
    if (g < 0) return;
    atomicMax(&g_po.maxk[g * CH + c], ukey(mx));
    atomicAdd(&g_po.sum[g * CH + c], sm);
    if (c == 0) atomicAdd(&g_po.cnt[g], (float)cnt);
}

// batch_index is sorted: accumulate runs per channel, flush only on graph change.
__global__ void k_pool(const int* __restrict__ batch) {
    int c  = threadIdx.x & 63;
    int rs = threadIdx.x >> 6;           // 0..3
    int base = blockIdx.x * 64;

    int curg = -1; float mx = -3.4e38f, sm = 0.0f; int cnt = 0;
    for (int r = rs; r < 64; r += 4) {
        int node = base + r;
        if (node >= NN) break;
        int g = batch[node];
        float v = g_act[(size_t)node * CH + c];
        if (g != curg) {
            pool_flush(curg, c, mx, sm, cnt);
            curg = g; mx = v; sm = v; cnt = 1;
        } else {
            mx = fmaxf(mx, v); sm += v; cnt++;
        }
    }
    pool_flush(curg, c, mx, sm, cnt);
}

__global__ void k_head(const float* __restrict__ Wout,
                       const float* __restrict__ bout,
                       float* __restrict__ out) {
    int g = blockIdx.x;
    int c = threadIdx.x;  // 64 threads
    float mx   = udec(g_po.maxk[g * CH + c]);
    float mean = g_po.sum[g * CH + c] / fmaxf(g_po.cnt[g], 1.0f);
    float v = mx * Wout[c] + mean * Wout[CH + c];
#pragma unroll
    for (int o = 16; o > 0; o >>= 1) v += __shfl_down_sync(0xFFFFFFFF, v, o);
    __shared__ float s[2];
    if ((c & 31) == 0) s[c >> 5] = v;
    __syncthreads();
    if (c == 0) out[g] = s[0] + s[1] + bout[0];
}

// ---------------- launch -------------------------------------------------------
extern "C" void kernel_launch(void* const* d_in, const int* in_sizes, int n_in,
                              void* d_out, int out_size) {
    const float* x     = (const float*)d_in[0];
    const int*   ei    = (const int*)  d_in[1];
    const float* ea    = (const float*)d_in[2];
    const int*   batch = (const int*)  d_in[3];
    const float* W0 = (const float*)d_in[4];  const float* b0 = (const float*)d_in[5];
    const float* W1 = (const float*)d_in[6];  const float* b1 = (const float*)d_in[7];
    const float* W2 = (const float*)d_in[8];  const float* b2 = (const float*)d_in[9];
    const float* W3 = (const float*)d_in[10]; const float* b3 = (const float*)d_in[11];
    const float* Wout = (const float*)d_in[12];
    const float* bout = (const float*)d_in[13];
    float* out = (float*)d_out;

    void* pz_addr = nullptr; void* po_addr = nullptr;
    cudaGetSymbolAddress(&pz_addr, g_pz);
    cudaGetSymbolAddress(&po_addr, g_po);

    const int TB = 256;
    const int gemm_blocks   = (NN + 63) / 64;                 // 782
    const int gather_blocks = (NN * 32 + TB - 1) / TB;        // 6250

    // preprocessing + CSR build (once; reused by all 4 layers)
    cudaMemsetAsync(pz_addr, 0, sizeof(PreZero), 0);
    k_pre_deg <<<(NE + TB - 1) / TB, TB>>>(ei, ea);
    k_scan_block<<<NB, SCAN_B>>>();
    k_scan_carry<<<1, 64>>>();
    k_scan_add<<<(NN + TB - 1) / TB, TB>>>();
    k_place<<<(NE + TB - 1) / TB, TB>>>(ei, ea);

    // layer 0: 128 -> 64 from x
    k_gemm<INCH, false><<<gemm_blocks, TB>>>(x, W0);
    k_gather<<<gather_blocks, TB>>>(b0);
    // layers 1..3: 64 -> 64 from g_act (already tanh'd), resolved in device code
    k_gemm<CH, true><<<gemm_blocks, TB>>>(nullptr, W1);
    k_gather<<<gather_blocks, TB>>>(b1);
    k_gemm<CH, true><<<gemm_blocks, TB>>>(nullptr, W2);
    k_gather<<<gather_blocks, TB>>>(b2);
    k_gemm<CH, true><<<gemm_blocks, TB>>>(nullptr, W3);
    k_gather<<<gather_blocks, TB>>>(b3);

    cudaMemsetAsync(po_addr, 0, sizeof(PoolZero), 0);
    k_pool<<<gemm_blocks, TB>>>(batch);
    k_head<<<NG, 64>>>(Wout, bout, out);
}

// round 6
// speedup vs baseline: 1.0545x; 1.0545x over previous
#include <cuda_runtime.h>
#include <cuda_bf16.h>
#include <cstdint>

#define NN   50000
#define NE   800000
#define NG   64
#define CH   64
#define INCH 128
#define SCAN_B 1024
#define NB   ((NN + SCAN_B - 1) / SCAN_B)   // 49

// ---------------- scratch (static device globals; no allocation) -------------
__device__ unsigned long long g_pd[NN];      // packed: count<<40 | wdeg fixed-point (memset 0)
struct PoolZero { unsigned maxk[NG * CH]; float sum[NG * CH]; float cnt[NG]; unsigned done; };
__device__ PoolZero g_po;                    // memset 0; ukey(x) > 0 for all reals
__device__ float g_dinv[NN];
__device__ float g_selfc[NN];
__device__ int   g_rowptr[NN + 1];
__device__ int   g_fill[NN];
__device__ int   g_bsum[64];
__device__ int2  g_edge[NE];                 // CSR-sorted (src, norm-bits)
__device__ __align__(16) float g_h[NN * CH];   // h = act @ W
__device__ __align__(16) float g_act[NN * CH]; // tanh(layer output)

// ---------------- helpers ----------------------------------------------------
__device__ __forceinline__ float acc_tanh(float x) {
    float e = __expf(-2.0f * fabsf(x));
    float t = __fdividef(1.0f - e, 1.0f + e);
    return copysignf(t, x);
}
// monotonic unsigned key: 0 == "below any real float"
__device__ __forceinline__ unsigned ukey(float f) {
    unsigned u = __float_as_uint(f);
    return (u & 0x80000000u) ? ~u : (u | 0x80000000u);
}
__device__ __forceinline__ float udec(unsigned u) {
    return __uint_as_float((u & 0x80000000u) ? (u & 0x7FFFFFFFu) : ~u);
}

#define FMA2(d, a, b) asm("fma.rn.f32x2 %0, %1, %2, %0;" : "+l"(d) : "l"(a), "l"(b))
__device__ __forceinline__ unsigned long long pack2(float x) {
    unsigned long long r;
    unsigned xi = __float_as_uint(x);
    asm("mov.b64 %0, {%1, %1};" : "=l"(r) : "r"(xi));
    return r;
}
__device__ __forceinline__ float2 unpack2(unsigned long long v) {
    unsigned lo, hi;
    asm("mov.b64 {%0, %1}, %2;" : "=r"(lo), "=r"(hi) : "l"(v));
    return make_float2(__uint_as_float(lo), __uint_as_float(hi));
}

// ---------------- preprocessing ----------------------------------------------
// one 64-bit RED per edge: count in bits [40..], wdeg as 2^21 fixed point below
__global__ void k_pre_deg(const int* __restrict__ ei, const float* __restrict__ w) {
    int e = blockIdx.x * blockDim.x + threadIdx.x;
    if (e < NE) {
        int dst = ei[NE + e];
        unsigned long long v = (1ull << 40) |
            (unsigned long long)__float2uint_rn(w[e] * 2097152.0f);
        atomicAdd(&g_pd[dst], v);
    }
}

// warp-shuffle scan over 1024 deg; also computes dinv/selfc
__global__ void k_scan_block() {
    __shared__ int wsum[32];
    int tid = threadIdx.x;
    int i   = blockIdx.x * SCAN_B + tid;
    int lane = tid & 31, wid = tid >> 5;
    unsigned long long pd = (i < NN) ? g_pd[i] : 0ull;
    int v = (int)(pd >> 40);
    int s = v;
#pragma unroll
    for (int o = 1; o < 32; o <<= 1) {
        int t = __shfl_up_sync(0xFFFFFFFFu, s, o);
        if (lane >= o) s += t;
    }
    if (lane == 31) wsum[wid] = s;
    __syncthreads();
    if (wid == 0) {
        int ws = wsum[lane];
#pragma unroll
        for (int o = 1; o < 32; o <<= 1) {
            int t = __shfl_up_sync(0xFFFFFFFFu, ws, o);
            if (lane >= o) ws += t;
        }
        wsum[lane] = ws;
    }
    __syncthreads();
    int off = wid ? wsum[wid - 1] : 0;
    if (i < NN) g_rowptr[i] = off + s - v;           // exclusive, pre-offset
    if (tid == SCAN_B - 1) g_bsum[blockIdx.x] = off + s;

    if (i < NN) {
        float wdeg = (float)(pd & ((1ull << 40) - 1ull)) * (1.0f / 2097152.0f);
        float r = rsqrtf(wdeg + 1.0f);               // +1 self-loop weight
        g_dinv[i]  = r;
        g_selfc[i] = r * r;
    }
}

// fused carry-scan + add: every block redoes the tiny 49-elem scan
__global__ void k_scan_add() {
    __shared__ int sc[64];
    int tid = threadIdx.x;
    if (tid < 32) {
        int v0 = (2 * tid     < NB) ? g_bsum[2 * tid]     : 0;
        int v1 = (2 * tid + 1 < NB) ? g_bsum[2 * tid + 1] : 0;
        int p = v0 + v1;
        int s = p;
#pragma unroll
        for (int o = 1; o < 32; o <<= 1) {
            int t = __shfl_up_sync(0xFFFFFFFFu, s, o);
            if (tid >= o) s += t;
        }
        sc[2 * tid]     = s - p;
        sc[2 * tid + 1] = s - p + v0;
    }
    __syncthreads();
    int i = blockIdx.x * blockDim.x + tid;
    if (i < NN) {
        int rp = g_rowptr[i] + sc[i >> 10];   // whole block shares one region
        g_rowptr[i] = rp;
        g_fill[i]   = rp;
    }
    if (i == 0) g_rowptr[NN] = NE;
}

__global__ void k_place(const int* __restrict__ ei, const float* __restrict__ w) {
    int e = blockIdx.x * blockDim.x + threadIdx.x;
    if (e < NE) {
        int src = ei[e];
        int dst = ei[NE + e];
        float nm = g_dinv[src] * w[e] * g_dinv[dst];
        int pos = atomicAdd(&g_fill[dst], 1);
        g_edge[pos] = make_int2(src, __float_as_int(nm));
    }
}

// ---------------- GEMM: h = A @ W (round-4 staging, f32x2 FMA) -----------------
// 256 threads; block = 64 rows x 64 cols; thread = 4 rows x 4 cols.
template <int K, bool FROM_ACT>
__global__ void k_gemm(const float* __restrict__ in, const float* __restrict__ W) {
    __shared__ __align__(16) float sA[64 * 68];   // [row][k], pad 68
    __shared__ __align__(16) float sW[64 * 64];   // [k][col]

    const int tid  = threadIdx.x;
    const int row0 = blockIdx.x * 64;
    const int rowg = tid >> 4;    // 0..15, 4 rows each
    const int colg = tid & 15;    // 0..15, 4 cols each

    const float* A = FROM_ACT ? (const float*)g_act : in;

    unsigned long long acc[4][2] = {{0ull,0ull},{0ull,0ull},{0ull,0ull},{0ull,0ull}};

    for (int kc = 0; kc < K; kc += 64) {
        // stage A tile [row][k]: contiguous float4 stores, conflict-free
#pragma unroll
        for (int idx = tid; idx < 64 * 16; idx += 256) {
            int rr = idx >> 4, k4 = (idx & 15) * 4;
            int grow = row0 + rr;
            float4 v = make_float4(0.f, 0.f, 0.f, 0.f);
            if (grow < NN) v = *(const float4*)(A + (size_t)grow * K + kc + k4);
            *(float4*)(sA + rr * 68 + k4) = v;
        }
        // stage W chunk (k-major)
#pragma unroll
        for (int idx = tid; idx < 64 * 16; idx += 256) {
            int rr = idx >> 4, c4 = (idx & 15) * 4;
            *(float4*)(sW + rr * 64 + c4) = *(const float4*)(W + (size_t)(kc + rr) * 64 + c4);
        }
        __syncthreads();

#pragma unroll
        for (int k = 0; k < 64; ++k) {
            const ulonglong2 wv = *(const ulonglong2*)(sW + k * 64 + colg * 4);
            unsigned long long pa0 = pack2(sA[(rowg * 4 + 0) * 68 + k]);
            unsigned long long pa1 = pack2(sA[(rowg * 4 + 1) * 68 + k]);
            unsigned long long pa2 = pack2(sA[(rowg * 4 + 2) * 68 + k]);
            unsigned long long pa3 = pack2(sA[(rowg * 4 + 3) * 68 + k]);
            FMA2(acc[0][0], pa0, wv.x); FMA2(acc[0][1], pa0, wv.y);
            FMA2(acc[1][0], pa1, wv.x); FMA2(acc[1][1], pa1, wv.y);
            FMA2(acc[2][0], pa2, wv.x); FMA2(acc[2][1], pa2, wv.y);
            FMA2(acc[3][0], pa3, wv.x); FMA2(acc[3][1], pa3, wv.y);
        }
        __syncthreads();
    }

    int row = row0 + rowg * 4;
#pragma unroll
    for (int i = 0; i < 4; ++i) {
        if (row + i < NN) {
            float2 lo = unpack2(acc[i][0]);
            float2 hi = unpack2(acc[i][1]);
            *(float4*)(g_h + (size_t)(row + i) * CH + colg * 4) =
                make_float4(lo.x, lo.y, hi.x, hi.y);
        }
    }
}

// ------- gather: act[i] = tanh(b + selfc[i]*h[i] + sum_e norm*h[src]) ----------
// one warp per node; 2 edges per iteration; lane = (half, c4): float4 channels.
__global__ void k_gather(const float* __restrict__ b) {
    int warp = (blockIdx.x * blockDim.x + threadIdx.x) >> 5;
    int lane = threadIdx.x & 31;
    if (warp >= NN) return;
    const int node = warp;
    const int beg  = g_rowptr[node];
    const int deg  = g_rowptr[node + 1] - beg;
    const int half = lane >> 4;
    const int c4   = (lane & 15) * 4;

    float ax = 0.f, ay = 0.f, az = 0.f, aw = 0.f;
    for (int ch = 0; ch < deg; ch += 32) {
        int rem = deg - ch;
        int n = rem < 32 ? rem : 32;
        int s = node; float nm = 0.0f;     // inactive lanes: nm=0 contributes nothing
        if (lane < n) {
            int2 e = g_edge[beg + ch + lane];
            s = e.x; nm = __int_as_float(e.y);
        }
        int npairs = (n + 1) >> 1;
#pragma unroll 4
        for (int j = 0; j < npairs; ++j) {
            int   se = __shfl_sync(0xFFFFFFFFu, s,  2 * j + half);
            float ne = __shfl_sync(0xFFFFFFFFu, nm, 2 * j + half);
            float4 hv = *(const float4*)(g_h + (size_t)se * CH + c4);
            ax += ne * hv.x; ay += ne * hv.y; az += ne * hv.z; aw += ne * hv.w;
        }
    }
    // combine the two edge-parity halves
    ax += __shfl_xor_sync(0xFFFFFFFFu, ax, 16);
    ay += __shfl_xor_sync(0xFFFFFFFFu, ay, 16);
    az += __shfl_xor_sync(0xFFFFFFFFu, az, 16);
    aw += __shfl_xor_sync(0xFFFFFFFFu, aw, 16);

    if (half == 0) {
        float sc = g_selfc[node];
        float4 hs = *(const float4*)(g_h + (size_t)node * CH + c4);
        float4 bb = *(const float4*)(b + c4);
        float4 o;
        o.x = acc_tanh(bb.x + sc * hs.x + ax);
        o.y = acc_tanh(bb.y + sc * hs.y + ay);
        o.z = acc_tanh(bb.z + sc * hs.z + az);
        o.w = acc_tanh(bb.w + sc * hs.w + aw);
        *(float4*)(g_act + (size_t)node * CH + c4) = o;
    }
}

// ---------------- pooling + fused head (g_po memset to 0) ----------------------
__device__ __forceinline__ void pool_flush(int g, int c, float mx, float sm, int cnt) {
    if (g < 0) return;
    atomicMax(&g_po.maxk[g * CH + c], ukey(mx));
    atomicAdd(&g_po.sum[g * CH + c], sm);
    if (c == 0) atomicAdd(&g_po.cnt[g], (float)cnt);
}

// batch_index is sorted: accumulate runs per channel, flush only on graph change.
// Last block computes the output head.
__global__ void k_pool(const int* __restrict__ batch,
                       const float* __restrict__ Wout,
                       const float* __restrict__ bout,
                       float* __restrict__ out) {
    int tid = threadIdx.x;
    int c  = tid & 63;
    int rs = tid >> 6;           // 0..3
    int base = blockIdx.x * 64;

    int curg = -1; float mx = -3.4e38f, sm = 0.0f; int cnt = 0;
    for (int r = rs; r < 64; r += 4) {
        int node = base + r;
        if (node >= NN) break;
        int g = batch[node];
        float v = g_act[(size_t)node * CH + c];
        if (g != curg) {
            pool_flush(curg, c, mx, sm, cnt);
            curg = g; mx = v; sm = v; cnt = 1;
        } else {
            mx = fmaxf(mx, v); sm += v; cnt++;
        }
    }
    pool_flush(curg, c, mx, sm, cnt);

    // last-block head
    __threadfence();
    __shared__ int s_last;
    __syncthreads();
    if (tid == 0) {
        unsigned t = atomicAdd(&g_po.done, 1u);
        s_last = (t == gridDim.x - 1) ? 1 : 0;
    }
    __syncthreads();
    if (!s_last) return;
    __threadfence();

    __shared__ float sh[8];
    int gl = tid >> 6;                 // 0..3
#pragma unroll
    for (int pass = 0; pass < NG / 4; ++pass) {
        int g = pass * 4 + gl;
        float mxv  = udec(g_po.maxk[g * CH + c]);
        float mean = g_po.sum[g * CH + c] / fmaxf(g_po.cnt[g], 1.0f);
        float v = mxv * Wout[c] + mean * Wout[CH + c];
#pragma unroll
        for (int o = 16; o > 0; o >>= 1) v += __shfl_down_sync(0xFFFFFFFFu, v, o);
        if ((tid & 31) == 0) sh[tid >> 5] = v;
        __syncthreads();
        if (tid < 4) out[pass * 4 + tid] = sh[2 * tid] + sh[2 * tid + 1] + bout[0];
        __syncthreads();
    }
}

// ---------------- launch -------------------------------------------------------
extern "C" void kernel_launch(void* const* d_in, const int* in_sizes, int n_in,
                              void* d_out, int out_size) {
    const float* x     = (const float*)d_in[0];
    const int*   ei    = (const int*)  d_in[1];
    const float* ea    = (const float*)d_in[2];
    const int*   batch = (const int*)  d_in[3];
    const float* W0 = (const float*)d_in[4];  const float* b0 = (const float*)d_in[5];
    const float* W1 = (const float*)d_in[6];  const float* b1 = (const float*)d_in[7];
    const float* W2 = (const float*)d_in[8];  const float* b2 = (const float*)d_in[9];
    const float* W3 = (const float*)d_in[10]; const float* b3 = (const float*)d_in[11];
    const float* Wout = (const float*)d_in[12];
    const float* bout = (const float*)d_in[13];
    float* out = (float*)d_out;

    void* pd_addr = nullptr; void* po_addr = nullptr;
    cudaGetSymbolAddress(&pd_addr, g_pd);
    cudaGetSymbolAddress(&po_addr, g_po);

    const int TB = 256;
    const int gemm_blocks   = (NN + 63) / 64;                 // 782
    const int gather_blocks = (NN * 32 + TB - 1) / TB;        // 6250

    // zero-init structs (graph memset nodes; deterministic)
    cudaMemsetAsync(po_addr, 0, sizeof(PoolZero), 0);
    cudaMemsetAsync(pd_addr, 0, sizeof(unsigned long long) * NN, 0);

    // preprocessing + CSR build (once; reused by all 4 layers)
    k_pre_deg <<<(NE + TB - 1) / TB, TB>>>(ei, ea);
    k_scan_block<<<NB, SCAN_B>>>();
    k_scan_add<<<(NN + TB - 1) / TB, TB>>>();
    k_place<<<(NE + TB - 1) / TB, TB>>>(ei, ea);

    // layer 0: 128 -> 64 from x
    k_gemm<INCH, false><<<gemm_blocks, TB>>>(x, W0);
    k_gather<<<gather_blocks, TB>>>(b0);
    // layers 1..3: 64 -> 64 from g_act (already tanh'd), resolved in device code
    k_gemm<CH, true><<<gemm_blocks, TB>>>(nullptr, W1);
    k_gather<<<gather_blocks, TB>>>(b1);
    k_gemm<CH, true><<<gemm_blocks, TB>>>(nullptr, W2);
    k_gather<<<gather_blocks, TB>>>(b2);
    k_gemm<CH, true><<<gemm_blocks, TB>>>(nullptr, W3);
    k_gather<<<gather_blocks, TB>>>(b3);

    // pooling + head (fused; last block writes out)
    k_pool<<<gemm_blocks, TB>>>(batch, Wout, bout, out);
}

// round 7
// speedup vs baseline: 1.1541x; 1.0944x over previous
#include <cuda_runtime.h>
#include <cuda_fp16.h>
#include <cstdint>

#define NN   50000
#define NE   800000
#define NG   64
#define CH   64
#define INCH 128
#define SCAN_B 1024
#define NB   ((NN + SCAN_B - 1) / SCAN_B)   // 49

// ---------------- scratch (static device globals; no allocation) -------------
__device__ unsigned long long g_pd[NN];      // packed: count<<40 | wdeg fixed-point (memset 0)
struct PoolZero { unsigned maxk[NG * CH]; float sum[NG * CH]; float cnt[NG]; unsigned done; };
__device__ PoolZero g_po;                    // memset 0; ukey(x) > 0 for all reals
__device__ float g_dinv[NN];
__device__ int   g_rowptr[NN + 1];
__device__ int   g_fill[NN];
__device__ int   g_bsum[64];
__device__ int2  g_edge[NE];                 // CSR-sorted (src, (w*dinv_src)-bits)
__device__ __align__(16) __half g_h[NN * CH];  // h = act @ W   (fp16 storage)
__device__ __align__(16) float g_act[NN * CH]; // tanh(layer output), fp32

// ---------------- helpers ----------------------------------------------------
__device__ __forceinline__ float acc_tanh(float x) {
    float e = __expf(-2.0f * fabsf(x));
    float t = __fdividef(1.0f - e, 1.0f + e);
    return copysignf(t, x);
}
// monotonic unsigned key: 0 == "below any real float"
__device__ __forceinline__ unsigned ukey(float f) {
    unsigned u = __float_as_uint(f);
    return (u & 0x80000000u) ? ~u : (u | 0x80000000u);
}
__device__ __forceinline__ float udec(unsigned u) {
    return __uint_as_float((u & 0x80000000u) ? (u & 0x7FFFFFFFu) : ~u);
}

#define FMA2(d, a, b) asm("fma.rn.f32x2 %0, %1, %2, %0;" : "+l"(d) : "l"(a), "l"(b))
__device__ __forceinline__ unsigned long long pack2(float x) {
    unsigned long long r;
    unsigned xi = __float_as_uint(x);
    asm("mov.b64 %0, {%1, %1};" : "=l"(r) : "r"(xi));
    return r;
}
__device__ __forceinline__ float2 unpack2(unsigned long long v) {
    unsigned lo, hi;
    asm("mov.b64 {%0, %1}, %2;" : "=r"(lo), "=r"(hi) : "l"(v));
    return make_float2(__uint_as_float(lo), __uint_as_float(hi));
}
__device__ __forceinline__ unsigned h2_to_u(__half2 h) {
    return *reinterpret_cast<unsigned*>(&h);
}
__device__ __forceinline__ __half2 u_to_h2(unsigned u) {
    return *reinterpret_cast<__half2*>(&u);
}

// ---------------- preprocessing ----------------------------------------------
// one 64-bit RED per edge: count in bits [40..], wdeg as 2^21 fixed point below
__global__ void k_pre_deg(const int* __restrict__ ei, const float* __restrict__ w) {
    int e = blockIdx.x * blockDim.x + threadIdx.x;
    if (e < NE) {
        int dst = ei[NE + e];
        unsigned long long v = (1ull << 40) |
            (unsigned long long)__float2uint_rn(w[e] * 2097152.0f);
        atomicAdd(&g_pd[dst], v);
    }
}

// warp-shuffle scan over 1024 deg; also computes dinv
__global__ void k_scan_block() {
    __shared__ int wsum[32];
    int tid = threadIdx.x;
    int i   = blockIdx.x * SCAN_B + tid;
    int lane = tid & 31, wid = tid >> 5;
    unsigned long long pd = (i < NN) ? g_pd[i] : 0ull;
    int v = (int)(pd >> 40);
    int s = v;
#pragma unroll
    for (int o = 1; o < 32; o <<= 1) {
        int t = __shfl_up_sync(0xFFFFFFFFu, s, o);
        if (lane >= o) s += t;
    }
    if (lane == 31) wsum[wid] = s;
    __syncthreads();
    if (wid == 0) {
        int ws = wsum[lane];
#pragma unroll
        for (int o = 1; o < 32; o <<= 1) {
            int t = __shfl_up_sync(0xFFFFFFFFu, ws, o);
            if (lane >= o) ws += t;
        }
        wsum[lane] = ws;
    }
    __syncthreads();
    int off = wid ? wsum[wid - 1] : 0;
    if (i < NN) g_rowptr[i] = off + s - v;           // exclusive, pre-offset
    if (tid == SCAN_B - 1) g_bsum[blockIdx.x] = off + s;

    if (i < NN) {
        float wdeg = (float)(pd & ((1ull << 40) - 1ull)) * (1.0f / 2097152.0f);
        g_dinv[i] = rsqrtf(wdeg + 1.0f);             // +1 self-loop weight
    }
}

// fused carry-scan + add: every block redoes the tiny 49-elem scan
__global__ void k_scan_add() {
    __shared__ int sc[64];
    int tid = threadIdx.x;
    if (tid < 32) {
        int v0 = (2 * tid     < NB) ? g_bsum[2 * tid]     : 0;
        int v1 = (2 * tid + 1 < NB) ? g_bsum[2 * tid + 1] : 0;
        int p = v0 + v1;
        int s = p;
#pragma unroll
        for (int o = 1; o < 32; o <<= 1) {
            int t = __shfl_up_sync(0xFFFFFFFFu, s, o);
            if (tid >= o) s += t;
        }
        sc[2 * tid]     = s - p;
        sc[2 * tid + 1] = s - p + v0;
    }
    __syncthreads();
    int i = blockIdx.x * blockDim.x + tid;
    if (i < NN) {
        int rp = g_rowptr[i] + sc[i >> 10];
        g_rowptr[i] = rp;
        g_fill[i]   = rp;
    }
    if (i == 0) g_rowptr[NN] = NE;
}

// stores (src, w*dinv[src]); dinv[dst] factored out into the gather epilogue
__global__ void k_place(const int* __restrict__ ei, const float* __restrict__ w) {
    int e = blockIdx.x * blockDim.x + threadIdx.x;
    if (e < NE) {
        int src = ei[e];
        int dst = ei[NE + e];
        float nm = g_dinv[src] * w[e];
        int pos = atomicAdd(&g_fill[dst], 1);
        g_edge[pos] = make_int2(src, __float_as_int(nm));
    }
}

// ---------------- GEMM: h = A @ W (f32x2 FMA), fp16 output ---------------------
// 256 threads; block = 64 rows x 64 cols; thread = 4 rows x 4 cols.
template <int K, bool FROM_ACT>
__global__ void k_gemm(const float* __restrict__ in, const float* __restrict__ W) {
    __shared__ __align__(16) float sA[64 * 68];   // [row][k], pad 68
    __shared__ __align__(16) float sW[64 * 64];   // [k][col]

    const int tid  = threadIdx.x;
    const int row0 = blockIdx.x * 64;
    const int rowg = tid >> 4;    // 0..15, 4 rows each
    const int colg = tid & 15;    // 0..15, 4 cols each

    const float* A = FROM_ACT ? (const float*)g_act : in;

    unsigned long long acc[4][2] = {{0ull,0ull},{0ull,0ull},{0ull,0ull},{0ull,0ull}};

    for (int kc = 0; kc < K; kc += 64) {
#pragma unroll
        for (int idx = tid; idx < 64 * 16; idx += 256) {
            int rr = idx >> 4, k4 = (idx & 15) * 4;
            int grow = row0 + rr;
            float4 v = make_float4(0.f, 0.f, 0.f, 0.f);
            if (grow < NN) v = *(const float4*)(A + (size_t)grow * K + kc + k4);
            *(float4*)(sA + rr * 68 + k4) = v;
        }
#pragma unroll
        for (int idx = tid; idx < 64 * 16; idx += 256) {
            int rr = idx >> 4, c4 = (idx & 15) * 4;
            *(float4*)(sW + rr * 64 + c4) = *(const float4*)(W + (size_t)(kc + rr) * 64 + c4);
        }
        __syncthreads();

#pragma unroll
        for (int k = 0; k < 64; ++k) {
            const ulonglong2 wv = *(const ulonglong2*)(sW + k * 64 + colg * 4);
            unsigned long long pa0 = pack2(sA[(rowg * 4 + 0) * 68 + k]);
            unsigned long long pa1 = pack2(sA[(rowg * 4 + 1) * 68 + k]);
            unsigned long long pa2 = pack2(sA[(rowg * 4 + 2) * 68 + k]);
            unsigned long long pa3 = pack2(sA[(rowg * 4 + 3) * 68 + k]);
            FMA2(acc[0][0], pa0, wv.x); FMA2(acc[0][1], pa0, wv.y);
            FMA2(acc[1][0], pa1, wv.x); FMA2(acc[1][1], pa1, wv.y);
            FMA2(acc[2][0], pa2, wv.x); FMA2(acc[2][1], pa2, wv.y);
            FMA2(acc[3][0], pa3, wv.x); FMA2(acc[3][1], pa3, wv.y);
        }
        __syncthreads();
    }

    int row = row0 + rowg * 4;
#pragma unroll
    for (int i = 0; i < 4; ++i) {
        if (row + i < NN) {
            float2 lo = unpack2(acc[i][0]);
            float2 hi = unpack2(acc[i][1]);
            uint2 st;
            st.x = h2_to_u(__float22half2_rn(lo));
            st.y = h2_to_u(__float22half2_rn(hi));
            *(uint2*)(g_h + (size_t)(row + i) * CH + colg * 4) = st;
        }
    }
}

// --- gather: act[i] = tanh(b + dinv_i*(sum_e w'_e*h[src] + dinv_i*h[i])) -------
// one warp per node; 2 edges per iteration; lane = (half, c4): 4 fp16 channels.
__global__ void k_gather(const float* __restrict__ b) {
    int warp = (blockIdx.x * blockDim.x + threadIdx.x) >> 5;
    int lane = threadIdx.x & 31;
    if (warp >= NN) return;
    const int node = warp;
    const int beg  = g_rowptr[node];
    const int deg  = g_rowptr[node + 1] - beg;
    const int half = lane >> 4;
    const int c4   = (lane & 15) * 4;

    float ax = 0.f, ay = 0.f, az = 0.f, aw = 0.f;
    for (int ch = 0; ch < deg; ch += 32) {
        int rem = deg - ch;
        int n = rem < 32 ? rem : 32;
        int s = node; float nm = 0.0f;     // inactive lanes: nm=0 contributes nothing
        if (lane < n) {
            int2 e = g_edge[beg + ch + lane];
            s = e.x; nm = __int_as_float(e.y);
        }
        int npairs = (n + 1) >> 1;
#pragma unroll 4
        for (int j = 0; j < npairs; ++j) {
            int   se = __shfl_sync(0xFFFFFFFFu, s,  2 * j + half);
            float ne = __shfl_sync(0xFFFFFFFFu, nm, 2 * j + half);
            uint2 hv = *(const uint2*)(g_h + (size_t)se * CH + c4);
            float2 f0 = __half22float2(u_to_h2(hv.x));
            float2 f1 = __half22float2(u_to_h2(hv.y));
            ax += ne * f0.x; ay += ne * f0.y; az += ne * f1.x; aw += ne * f1.y;
        }
    }
    // combine the two edge-parity halves
    ax += __shfl_xor_sync(0xFFFFFFFFu, ax, 16);
    ay += __shfl_xor_sync(0xFFFFFFFFu, ay, 16);
    az += __shfl_xor_sync(0xFFFFFFFFu, az, 16);
    aw += __shfl_xor_sync(0xFFFFFFFFu, aw, 16);

    if (half == 0) {
        float dv = g_dinv[node];
        uint2 hu = *(const uint2*)(g_h + (size_t)node * CH + c4);
        float2 h0 = __half22float2(u_to_h2(hu.x));
        float2 h1 = __half22float2(u_to_h2(hu.y));
        float4 bb = *(const float4*)(b + c4);
        float4 o;
        o.x = acc_tanh(bb.x + dv * (ax + dv * h0.x));
        o.y = acc_tanh(bb.y + dv * (ay + dv * h0.y));
        o.z = acc_tanh(bb.z + dv * (az + dv * h1.x));
        o.w = acc_tanh(bb.w + dv * (aw + dv * h1.y));
        *(float4*)(g_act + (size_t)node * CH + c4) = o;
    }
}

// ---------------- pooling + fused head (g_po memset to 0) ----------------------
__device__ __forceinline__ void pool_flush(int g, int c, float mx, float sm, int cnt) {
    if (g < 0) return;
    atomicMax(&g_po.maxk[g * CH + c], ukey(mx));
    atomicAdd(&g_po.sum[g * CH + c], sm);
    if (c == 0) atomicAdd(&g_po.cnt[g], (float)cnt);
}

__global__ void k_pool(const int* __restrict__ batch,
                       const float* __restrict__ Wout,
                       const float* __restrict__ bout,
                       float* __restrict__ out) {
    int tid = threadIdx.x;
    int c  = tid & 63;
    int rs = tid >> 6;           // 0..3
    int base = blockIdx.x * 64;

    int curg = -1; float mx = -3.4e38f, sm = 0.0f; int cnt = 0;
    for (int r = rs; r < 64; r += 4) {
        int node = base + r;
        if (node >= NN) break;
        int g = batch[node];
        float v = g_act[(size_t)node * CH + c];
        if (g != curg) {
            pool_flush(curg, c, mx, sm, cnt);
            curg = g; mx = v; sm = v; cnt = 1;
        } else {
            mx = fmaxf(mx, v); sm += v; cnt++;
        }
    }
    pool_flush(curg, c, mx, sm, cnt);

    // last-block head
    __threadfence();
    __shared__ int s_last;
    __syncthreads();
    if (tid == 0) {
        unsigned t = atomicAdd(&g_po.done, 1u);
        s_last = (t == gridDim.x - 1) ? 1 : 0;
    }
    __syncthreads();
    if (!s_last) return;
    __threadfence();

    __shared__ float sh[8];
    int gl = tid >> 6;                 // 0..3
#pragma unroll
    for (int pass = 0; pass < NG / 4; ++pass) {
        int g = pass * 4 + gl;
        float mxv  = udec(g_po.maxk[g * CH + c]);
        float mean = g_po.sum[g * CH + c] / fmaxf(g_po.cnt[g], 1.0f);
        float v = mxv * Wout[c] + mean * Wout[CH + c];
#pragma unroll
        for (int o = 16; o > 0; o >>= 1) v += __shfl_down_sync(0xFFFFFFFFu, v, o);
        if ((tid & 31) == 0) sh[tid >> 5] = v;
        __syncthreads();
        if (tid < 4) out[pass * 4 + tid] = sh[2 * tid] + sh[2 * tid + 1] + bout[0];
        __syncthreads();
    }
}

// ---------------- launch -------------------------------------------------------
extern "C" void kernel_launch(void* const* d_in, const int* in_sizes, int n_in,
                              void* d_out, int out_size) {
    const float* x     = (const float*)d_in[0];
    const int*   ei    = (const int*)  d_in[1];
    const float* ea    = (const float*)d_in[2];
    const int*   batch = (const int*)  d_in[3];
    const float* W0 = (const float*)d_in[4];  const float* b0 = (const float*)d_in[5];
    const float* W1 = (const float*)d_in[6];  const float* b1 = (const float*)d_in[7];
    const float* W2 = (const float*)d_in[8];  const float* b2 = (const float*)d_in[9];
    const float* W3 = (const float*)d_in[10]; const float* b3 = (const float*)d_in[11];
    const float* Wout = (const float*)d_in[12];
    const float* bout = (const float*)d_in[13];
    float* out = (float*)d_out;

    void* pd_addr = nullptr; void* po_addr = nullptr;
    cudaGetSymbolAddress(&pd_addr, g_pd);
    cudaGetSymbolAddress(&po_addr, g_po);

    const int TB = 256;
    const int gemm_blocks   = (NN + 63) / 64;                 // 782
    const int gather_blocks = (NN * 32 + TB - 1) / TB;        // 6250

    // zero-init structs (graph memset nodes; deterministic)
    cudaMemsetAsync(po_addr, 0, sizeof(PoolZero), 0);
    cudaMemsetAsync(pd_addr, 0, sizeof(unsigned long long) * NN, 0);

    // preprocessing + CSR build (once; reused by all 4 layers)
    k_pre_deg <<<(NE + TB - 1) / TB, TB>>>(ei, ea);
    k_scan_block<<<NB, SCAN_B>>>();
    k_scan_add<<<(NN + TB - 1) / TB, TB>>>();
    k_place<<<(NE + TB - 1) / TB, TB>>>(ei, ea);

    // layer 0: 128 -> 64 from x
    k_gemm<INCH, false><<<gemm_blocks, TB>>>(x, W0);
    k_gather<<<gather_blocks, TB>>>(b0);
    // layers 1..3: 64 -> 64 from g_act (already tanh'd), resolved in device code
    k_gemm<CH, true><<<gemm_blocks, TB>>>(nullptr, W1);
    k_gather<<<gather_blocks, TB>>>(b1);
    k_gemm<CH, true><<<gemm_blocks, TB>>>(nullptr, W2);
    k_gather<<<gather_blocks, TB>>>(b2);
    k_gemm<CH, true><<<gemm_blocks, TB>>>(nullptr, W3);
    k_gather<<<gather_blocks, TB>>>(b3);

    // pooling + head (fused; last block writes out)
    k_pool<<<gemm_blocks, TB>>>(batch, Wout, bout, out);
}